// round 14
// baseline (speedup 1.0000x reference)
#include <cuda_runtime.h>
#include <cstdint>

#define BH    8
#define DK    64
#define DVV   64
#define NSEQ  2048
#define MF    128
#define CHUNK 128
#define NC    16
#define VP    72          // DV padded: col 64 = ones (z / norm), 65..71 = 0

#define PHI_SCALE 0.08838834764831845f   // 1/sqrt(128)

// Per-(head,chunk) fused state [S | z | pad] : [m][VP], fp32.
// kB converts to exclusive prefix over chunks.
__device__ float g_S[BH * NC * MF * VP];   // 4.7 MB

// ---------------------------------------------------------------------------
__device__ __forceinline__ uint32_t f2tf(float f) {
    uint32_t r; asm("cvt.rna.tf32.f32 %0, %1;" : "=r"(r) : "f"(f)); return r;
}
__device__ __forceinline__ void mma8(float* d, const uint32_t* A, const uint32_t* B) {
    asm volatile("mma.sync.aligned.m16n8k8.row.col.f32.tf32.tf32.f32 "
                 "{%0,%1,%2,%3}, {%4,%5,%6,%7}, {%8,%9}, {%0,%1,%2,%3};"
                 : "+f"(d[0]), "+f"(d[1]), "+f"(d[2]), "+f"(d[3])
                 : "r"(A[0]), "r"(A[1]), "r"(A[2]), "r"(A[3]), "r"(B[0]), "r"(B[1]));
}

// Smem strides (words), chosen so fragment LDS are bank-conflict-free:
// A-operand row stride ≡ 4 (mod 32); B-operand row stride ≡ 8 (mod 32).
#define STR_KQ 68    // [i][d]  A
#define STR_F  136   // [d][m]  B (kC)
#define STR_F2 72    // [d][m]  B (kA half-width F)
#define STR_PT 132   // [m][i]  A (kA phi^T)
#define STR_V  72    // [i][v]  B
#define STR_PQ 132   // [i][m]  A
#define STR_PK 136   // [m][j]  B
#define STR_SC 132   // [i][j]  A
#define STR_ST 72    // [m][v]  B

// ===========================================================================
// Kernel A (split grid, 256 CTAs = (c, mh) x h): each CTA computes
// phi[:, 64*mh : 64*mh+64] = relu(Kc F_half^T)*s  and the matching 64 rows of
// the chunk state [S|z] = phi^T [V;1].  Zero duplicated MMA work vs the fused
// version; smem 88KB -> 2 CTAs/SM resident.
// ===========================================================================
#define A_K   0        // K [i][d] 128x68 = 8704 ; reused as phiT [m][i] 64x132 = 8448
#define A_F   8704     // F_half [d][m] 64x72 = 4608
#define A_V   13312    // V+ [i][v] 128x72 = 9216
#define A_SMW 22528
#define A_SMB (A_SMW * 4)

__global__ void __launch_bounds__(256)
kA(const float* __restrict__ keys, const float* __restrict__ values,
   const float* __restrict__ feat)
{
    extern __shared__ uint32_t sm[];
    const int t = threadIdx.x, w = t >> 5, lane = t & 31;
    const int g = lane >> 2, tg = lane & 3;
    const int bc = blockIdx.x, c = bc >> 1, mh = bc & 1, h = blockIdx.y;
    const int nbase = c * CHUNK, mbase = mh * 64;

    // Stage K, F_half, V+ (tf32-rounded)
    for (int idx = t; idx < DK * CHUNK; idx += 256) {
        int i = idx & 127, d = idx >> 7;
        sm[A_K + i * STR_KQ + d] = f2tf(keys[(h * DK + d) * NSEQ + nbase + i]);
    }
    for (int idx = t; idx < 64 * DK; idx += 256) {
        int d = idx & 63, m = idx >> 6;
        sm[A_F + d * STR_F2 + m] = f2tf(feat[(mbase + m) * DK + d]);
    }
    for (int idx = t; idx < DVV * CHUNK; idx += 256) {
        int i = idx & 127, v = idx >> 7;
        sm[A_V + i * STR_V + v] = f2tf(values[(h * DVV + v) * NSEQ + nbase + i]);
    }
    for (int idx = t; idx < CHUNK * 8; idx += 256) {
        int i = idx >> 3, v = 64 + (idx & 7);
        sm[A_V + i * STR_V + v] = (v == 64) ? 0x3F800000u : 0u;
    }
    __syncthreads();

    // GEMM1: phi[i][m_local], K=64; 8 warps, tiles 32x32 (4 i-tiles x 2 m-tiles)
    {
        const int i0 = (w & 3) * 32, n0 = (w >> 2) * 32;
        float D[2][4][4] = {};
        for (int kk = 0; kk < 64; kk += 8) {
            uint32_t A[2][4], B[4][2];
            #pragma unroll
            for (int ms = 0; ms < 2; ms++) {
                int r0 = i0 + ms * 16 + g;
                A[ms][0] = sm[A_K + r0 * STR_KQ + kk + tg];
                A[ms][1] = sm[A_K + (r0 + 8) * STR_KQ + kk + tg];
                A[ms][2] = sm[A_K + r0 * STR_KQ + kk + tg + 4];
                A[ms][3] = sm[A_K + (r0 + 8) * STR_KQ + kk + tg + 4];
            }
            #pragma unroll
            for (int ns = 0; ns < 4; ns++) {
                B[ns][0] = sm[A_F + (kk + tg) * STR_F2 + n0 + ns * 8 + g];
                B[ns][1] = sm[A_F + (kk + tg + 4) * STR_F2 + n0 + ns * 8 + g];
            }
            #pragma unroll
            for (int ms = 0; ms < 2; ms++)
                #pragma unroll
                for (int ns = 0; ns < 4; ns++) mma8(D[ms][ns], A[ms], B[ns]);
        }
        __syncthreads();   // all K/F reads done -> region reusable for phiT
        // Epilogue: relu*scale -> phiT [m_local][i] over the K region
        #pragma unroll
        for (int ms = 0; ms < 2; ms++)
            #pragma unroll
            for (int ns = 0; ns < 4; ns++)
                #pragma unroll
                for (int e = 0; e < 4; e++) {
                    int row = i0 + ms * 16 + g + ((e >> 1) << 3);
                    int col = n0 + ns * 8 + tg * 2 + (e & 1);
                    sm[A_K + col * STR_PT + row] =
                        f2tf(fmaxf(D[ms][ns][e], 0.f) * PHI_SCALE);
                }
    }
    __syncthreads();

    // GEMM2: [S|z] rows [mbase, mbase+64), K=128; 4 m-tiles x 2 v-halves
    {
        const int m0 = (w >> 1) * 16, half = w & 1;
        const int nsB = half ? 5 : 0, nsC = half ? 4 : 5;
        float D[5][4] = {};
        for (int kk = 0; kk < CHUNK; kk += 8) {
            uint32_t A[4];
            A[0] = sm[A_K + (m0 + g) * STR_PT + kk + tg];
            A[1] = sm[A_K + (m0 + g + 8) * STR_PT + kk + tg];
            A[2] = sm[A_K + (m0 + g) * STR_PT + kk + tg + 4];
            A[3] = sm[A_K + (m0 + g + 8) * STR_PT + kk + tg + 4];
            #pragma unroll
            for (int s = 0; s < 5; s++) {
                if (s >= nsC) break;
                int ns = nsB + s;
                uint32_t B[2];
                B[0] = sm[A_V + (kk + tg) * STR_V + ns * 8 + g];
                B[1] = sm[A_V + (kk + tg + 4) * STR_V + ns * 8 + g];
                mma8(D[s], A, B);
            }
        }
        float* Sg = g_S + (size_t)(h * NC + c) * MF * VP;
        #pragma unroll
        for (int s = 0; s < 5; s++) {
            if (s >= nsC) break;
            #pragma unroll
            for (int e = 0; e < 4; e++) {
                int row = mbase + m0 + g + ((e >> 1) << 3);
                int col = (nsB + s) * 8 + tg * 2 + (e & 1);
                Sg[row * VP + col] = D[s][e];
            }
        }
    }
}

// ===========================================================================
// Kernel B: exclusive prefix over chunks of g_S (elementwise)
// ===========================================================================
__global__ void __launch_bounds__(256, 1) kB()
{
    const int h = blockIdx.x, idx = blockIdx.y * 256 + threadIdx.x;  // < 9216
    float* base = g_S + (size_t)h * NC * MF * VP + idx;
    float v[NC];
    #pragma unroll
    for (int c = 0; c < NC; c++) v[c] = base[c * (MF * VP)];
    float run = 0.f;
    #pragma unroll
    for (int c = 0; c < NC; c++) { base[c * (MF * VP)] = run; run += v[c]; }
}

// ===========================================================================
// Kernel C: phi_k, phi_q, scores (masked, causal-skip), out = phiQ.S+ + Sc.V+
// (pass 2 truncated at the diagonal), norm, store  — verbatim from R11
// ===========================================================================
#define C_KQ  0                      // 128x68 = 8704 -> later St 128x72 @0
#define C_F   8704                   // 64x136 = 8704 -> later (St spills into)
#define C_ST  0                      // 128x72 = 9216
#define C_V   9216                   // 128x72 = 9216
#define C_PQ  18432                  // 128x132 = 16896
#define C_PK  35328                  // 128x136 = 17408 (later Sc 128x132)
#define C_SMW 52736
#define C_SMB (C_SMW * 4)

__global__ void __launch_bounds__(256, 1)
kC(const float* __restrict__ queries, const float* __restrict__ keys,
   const float* __restrict__ values, const float* __restrict__ feat,
   float* __restrict__ out)
{
    extern __shared__ uint32_t sm[];
    const int t = threadIdx.x, w = t >> 5, lane = t & 31;
    const int g = lane >> 2, tg = lane & 3;
    const int c = blockIdx.x, h = blockIdx.y, nbase = c * CHUNK;

    // a) stage K, F
    for (int idx = t; idx < DK * CHUNK; idx += 256) {
        int i = idx & 127, d = idx >> 7;
        sm[C_KQ + i * STR_KQ + d] = f2tf(keys[(h * DK + d) * NSEQ + nbase + i]);
    }
    for (int idx = t; idx < MF * DK; idx += 256) {
        int d = idx & 63, m = idx >> 6;
        sm[C_F + d * STR_F + m] = f2tf(feat[m * DK + d]);
    }
    __syncthreads();

    const int pm0 = (w & 3) * 32, pn0 = (w >> 2) * 64;

    // b) GEMM phi_k (frags)
    float DP[2][8][4] = {};
    for (int kk = 0; kk < 64; kk += 8) {
        uint32_t A[2][4], B[8][2];
        #pragma unroll
        for (int ms = 0; ms < 2; ms++) {
            int r0 = pm0 + ms * 16 + g;
            A[ms][0] = sm[C_KQ + r0 * STR_KQ + kk + tg];
            A[ms][1] = sm[C_KQ + (r0 + 8) * STR_KQ + kk + tg];
            A[ms][2] = sm[C_KQ + r0 * STR_KQ + kk + tg + 4];
            A[ms][3] = sm[C_KQ + (r0 + 8) * STR_KQ + kk + tg + 4];
        }
        #pragma unroll
        for (int ns = 0; ns < 8; ns++) {
            B[ns][0] = sm[C_F + (kk + tg) * STR_F + pn0 + ns * 8 + g];
            B[ns][1] = sm[C_F + (kk + tg + 4) * STR_F + pn0 + ns * 8 + g];
        }
        #pragma unroll
        for (int ms = 0; ms < 2; ms++)
            #pragma unroll
            for (int ns = 0; ns < 8; ns++) mma8(DP[ms][ns], A[ms], B[ns]);
    }
    __syncthreads();   // all reads of K done

    // c) epilogue phi_k -> sPK[m][j] (transposed); restage Q into C_KQ
    #pragma unroll
    for (int ms = 0; ms < 2; ms++)
        #pragma unroll
        for (int ns = 0; ns < 8; ns++)
            #pragma unroll
            for (int e = 0; e < 4; e++) {
                int rj = pm0 + ms * 16 + g + ((e >> 1) << 3);
                int cm = pn0 + ns * 8 + tg * 2 + (e & 1);
                sm[C_PK + cm * STR_PK + rj] =
                    f2tf(fmaxf(DP[ms][ns][e], 0.f) * PHI_SCALE);
            }
    for (int idx = t; idx < DK * CHUNK; idx += 256) {
        int i = idx & 127, d = idx >> 7;
        sm[C_KQ + i * STR_KQ + d] = f2tf(queries[(h * DK + d) * NSEQ + nbase + i]);
    }
    __syncthreads();

    // d) GEMM phi_q (frags)
    #pragma unroll
    for (int ms = 0; ms < 2; ms++)
        #pragma unroll
        for (int ns = 0; ns < 8; ns++)
            #pragma unroll
            for (int e = 0; e < 4; e++) DP[ms][ns][e] = 0.f;
    for (int kk = 0; kk < 64; kk += 8) {
        uint32_t A[2][4], B[8][2];
        #pragma unroll
        for (int ms = 0; ms < 2; ms++) {
            int r0 = pm0 + ms * 16 + g;
            A[ms][0] = sm[C_KQ + r0 * STR_KQ + kk + tg];
            A[ms][1] = sm[C_KQ + (r0 + 8) * STR_KQ + kk + tg];
            A[ms][2] = sm[C_KQ + r0 * STR_KQ + kk + tg + 4];
            A[ms][3] = sm[C_KQ + (r0 + 8) * STR_KQ + kk + tg + 4];
        }
        #pragma unroll
        for (int ns = 0; ns < 8; ns++) {
            B[ns][0] = sm[C_F + (kk + tg) * STR_F + pn0 + ns * 8 + g];
            B[ns][1] = sm[C_F + (kk + tg + 4) * STR_F + pn0 + ns * 8 + g];
        }
        #pragma unroll
        for (int ms = 0; ms < 2; ms++)
            #pragma unroll
            for (int ns = 0; ns < 8; ns++) mma8(DP[ms][ns], A[ms], B[ns]);
    }
    __syncthreads();   // all reads of Q/F done -> C_KQ/C_F reusable

    // e) epilogue phi_q -> sPQ[i][m]; stage St+ (prefix [S|z]) and V+
    #pragma unroll
    for (int ms = 0; ms < 2; ms++)
        #pragma unroll
        for (int ns = 0; ns < 8; ns++)
            #pragma unroll
            for (int e = 0; e < 4; e++) {
                int ri = pm0 + ms * 16 + g + ((e >> 1) << 3);
                int cm = pn0 + ns * 8 + tg * 2 + (e & 1);
                sm[C_PQ + ri * STR_PQ + cm] =
                    f2tf(fmaxf(DP[ms][ns][e], 0.f) * PHI_SCALE);
            }
    {
        const float* Sg = g_S + (size_t)(h * NC + c) * MF * VP;
        for (int idx = t; idx < MF * VP; idx += 256)
            sm[C_ST + idx] = f2tf(Sg[idx]);          // [m][v], stride 72 native
        for (int idx = t; idx < DVV * CHUNK; idx += 256) {
            int j = idx & 127, v = idx >> 7;
            sm[C_V + j * STR_V + v] = f2tf(values[(h * DVV + v) * NSEQ + nbase + j]);
        }
        for (int idx = t; idx < CHUNK * 8; idx += 256) {
            int j = idx >> 3, v = 64 + (idx & 7);
            sm[C_V + j * STR_V + v] = (v == 64) ? 0x3F800000u : 0u;
        }
    }
    __syncthreads();

    // f) GEMM scores: A=sPQ, B=sPK, K=128 (frags in DP).
    // Causal skip: warps whose whole 32x64 tile lies above the diagonal
    // (pn0 > pm0 + 31, i.e. warps 4 and 5) do no MMAs — DP stays 0, and the
    // mask epilogue writes the identical zeros.
    #pragma unroll
    for (int ms = 0; ms < 2; ms++)
        #pragma unroll
        for (int ns = 0; ns < 8; ns++)
            #pragma unroll
            for (int e = 0; e < 4; e++) DP[ms][ns][e] = 0.f;
    if (pn0 <= pm0 + 31) {
        for (int kk = 0; kk < CHUNK; kk += 8) {
            uint32_t A[2][4], B[8][2];
            #pragma unroll
            for (int ms = 0; ms < 2; ms++) {
                int r0 = pm0 + ms * 16 + g;
                A[ms][0] = sm[C_PQ + r0 * STR_PQ + kk + tg];
                A[ms][1] = sm[C_PQ + (r0 + 8) * STR_PQ + kk + tg];
                A[ms][2] = sm[C_PQ + r0 * STR_PQ + kk + tg + 4];
                A[ms][3] = sm[C_PQ + (r0 + 8) * STR_PQ + kk + tg + 4];
            }
            #pragma unroll
            for (int ns = 0; ns < 8; ns++) {
                B[ns][0] = sm[C_PK + (kk + tg) * STR_PK + pn0 + ns * 8 + g];
                B[ns][1] = sm[C_PK + (kk + tg + 4) * STR_PK + pn0 + ns * 8 + g];
            }
            #pragma unroll
            for (int ms = 0; ms < 2; ms++)
                #pragma unroll
                for (int ns = 0; ns < 8; ns++) mma8(DP[ms][ns], A[ms], B[ns]);
        }
    }
    __syncthreads();   // all reads of sPK done

    // g) epilogue scores: causal mask -> sSc[i][j] (overwrites C_PK region)
    #pragma unroll
    for (int ms = 0; ms < 2; ms++)
        #pragma unroll
        for (int ns = 0; ns < 8; ns++)
            #pragma unroll
            for (int e = 0; e < 4; e++) {
                int ri = pm0 + ms * 16 + g + ((e >> 1) << 3);
                int cj = pn0 + ns * 8 + tg * 2 + (e & 1);
                float s = (cj <= ri) ? DP[ms][ns][e] : 0.f;
                sm[C_PK + ri * STR_SC + cj] = f2tf(s);
            }
    __syncthreads();

    // h) GEMM out: [out|norm][i][v+] = phiQ.St+ + Sc.V+ ; warp tile 16x72
    {
        const int i0 = w * 16;
        float D[9][4] = {};
        for (int kk = 0; kk < CHUNK; kk += 8) {       // pass 1: phiQ . St+
            uint32_t A[4];
            A[0] = sm[C_PQ + (i0 + g) * STR_PQ + kk + tg];
            A[1] = sm[C_PQ + (i0 + g + 8) * STR_PQ + kk + tg];
            A[2] = sm[C_PQ + (i0 + g) * STR_PQ + kk + tg + 4];
            A[3] = sm[C_PQ + (i0 + g + 8) * STR_PQ + kk + tg + 4];
            #pragma unroll
            for (int ns = 0; ns < 9; ns++) {
                uint32_t B[2];
                B[0] = sm[C_ST + (kk + tg) * STR_ST + ns * 8 + g];
                B[1] = sm[C_ST + (kk + tg + 4) * STR_ST + ns * 8 + g];
                mma8(D[ns], A, B);
            }
        }
        // pass 2: Sc . V+, k-loop truncated at the diagonal — Sc[i][j] = 0 for
        // j > i, and rows of this warp end at i0+15, so only (i0+16)/8 k-steps
        // contribute nonzero terms.
        const int kend = i0 + 16;
        for (int kk = 0; kk < kend; kk += 8) {
            uint32_t A[4];
            A[0] = sm[C_PK + (i0 + g) * STR_SC + kk + tg];
            A[1] = sm[C_PK + (i0 + g + 8) * STR_SC + kk + tg];
            A[2] = sm[C_PK + (i0 + g) * STR_SC + kk + tg + 4];
            A[3] = sm[C_PK + (i0 + g + 8) * STR_SC + kk + tg + 4];
            #pragma unroll
            for (int ns = 0; ns < 9; ns++) {
                uint32_t B[2];
                B[0] = sm[C_V + (kk + tg) * STR_V + ns * 8 + g];
                B[1] = sm[C_V + (kk + tg + 4) * STR_V + ns * 8 + g];
                mma8(D[ns], A, B);
            }
        }
        // i) norm = column 64 (ns=8, tg=0, e=0/2) -> broadcast within row group
        float nlo = __shfl_sync(0xffffffffu, D[8][0], lane & 28);
        float nhi = __shfl_sync(0xffffffffu, D[8][2], lane & 28);
        float ilo = 1.f / nlo, ihi = 1.f / nhi;
        #pragma unroll
        for (int ns = 0; ns < 8; ns++)
            #pragma unroll
            for (int e = 0; e < 4; e++) {
                int ri = i0 + g + ((e >> 1) << 3);
                int v  = ns * 8 + tg * 2 + (e & 1);
                out[(h * DVV + v) * NSEQ + nbase + ri] =
                    D[ns][e] * ((e >> 1) ? ihi : ilo);
            }
    }
}

// ===========================================================================
extern "C" void kernel_launch(void* const* d_in, const int* in_sizes, int n_in,
                              void* d_out, int out_size)
{
    const float* keys    = (const float*)d_in[0];
    const float* values  = (const float*)d_in[1];
    const float* queries = (const float*)d_in[2];
    const float* feat    = (const float*)d_in[3];
    float* out = (float*)d_out;

    cudaFuncSetAttribute(kA, cudaFuncAttributeMaxDynamicSharedMemorySize, A_SMB);
    cudaFuncSetAttribute(kC, cudaFuncAttributeMaxDynamicSharedMemorySize, C_SMB);

    kA<<<dim3(NC * 2, BH), 256, A_SMB>>>(keys, values, feat);
    kB<<<dim3(BH, 36), 256>>>();
    kC<<<dim3(NC, BH), 256, C_SMB>>>(queries, keys, values, feat, out);
}

// round 15
// speedup vs baseline: 1.1161x; 1.1161x over previous
#include <cuda_runtime.h>
#include <cstdint>

#define BH    8
#define DK    64
#define DVV   64
#define NSEQ  2048
#define MF    128
#define CHUNK 128
#define NC    16
#define VP    72          // DV padded: col 64 = ones (z / norm), 65..71 = 0

#define PHI_SCALE 0.08838834764831845f   // 1/sqrt(128)

// Per-(head,chunk) fused state [S | z | pad] : [m][VP], fp32.
// kB converts to exclusive prefix over chunks.
__device__ float g_S[BH * NC * MF * VP];   // 4.7 MB

// ---------------------------------------------------------------------------
__device__ __forceinline__ uint32_t f2tf(float f) {
    uint32_t r; asm("cvt.rna.tf32.f32 %0, %1;" : "=r"(r) : "f"(f)); return r;
}
__device__ __forceinline__ void mma8(float* d, const uint32_t* A, const uint32_t* B) {
    asm volatile("mma.sync.aligned.m16n8k8.row.col.f32.tf32.tf32.f32 "
                 "{%0,%1,%2,%3}, {%4,%5,%6,%7}, {%8,%9}, {%0,%1,%2,%3};"
                 : "+f"(d[0]), "+f"(d[1]), "+f"(d[2]), "+f"(d[3])
                 : "r"(A[0]), "r"(A[1]), "r"(A[2]), "r"(A[3]), "r"(B[0]), "r"(B[1]));
}

// Smem strides (words), chosen so fragment LDS are bank-conflict-free:
// A-operand row stride ≡ 4 (mod 32); B-operand row stride ≡ 8 (mod 32).
#define STR_KQ 68    // [i][d]  A
#define STR_F  136   // [d][m]  B
#define STR_PT 132   // [m][i]  A (kA phi^T)
#define STR_V  72    // [i][v]  B
#define STR_PQ 132   // [i][m]  A
#define STR_PK 136   // [m][j]  B
#define STR_SC 132   // [i][j]  A
#define STR_ST 72    // [m][v]  B

// ===========================================================================
// Kernel A: per (h,c): phi = relu(Kc F^T)*s ;  [S|z] = phi^T [V;1]
// ===========================================================================
#define A_K   0                       // 128 x 68  = 8704
#define A_F   8704                    // 64 x 136  = 8704
#define A_PT  17408                   // 128 x 132 = 16896
#define A_V   34304                   // 128 x 72  = 9216
#define A_SMW 43520
#define A_SMB (A_SMW * 4)

__global__ void __launch_bounds__(256, 1)
kA(const float* __restrict__ keys, const float* __restrict__ values,
   const float* __restrict__ feat)
{
    extern __shared__ uint32_t sm[];
    const int t = threadIdx.x, w = t >> 5, lane = t & 31;
    const int g = lane >> 2, tg = lane & 3;
    const int c = blockIdx.x, h = blockIdx.y, nbase = c * CHUNK;

    // Stage (tf32-rounded)
    for (int idx = t; idx < DK * CHUNK; idx += 256) {
        int i = idx & 127, d = idx >> 7;
        sm[A_K + i * STR_KQ + d] = f2tf(keys[(h * DK + d) * NSEQ + nbase + i]);
    }
    for (int idx = t; idx < MF * DK; idx += 256) {
        int d = idx & 63, m = idx >> 6;
        sm[A_F + d * STR_F + m] = f2tf(feat[m * DK + d]);
    }
    // V staged 4 v-values per thread: 4 coalesced LDG + one STS.128
    for (int idx = t; idx < (DVV / 4) * CHUNK; idx += 256) {
        int i = idx & 127, v4 = (idx >> 7) << 2;
        float a = values[(h * DVV + v4 + 0) * NSEQ + nbase + i];
        float b = values[(h * DVV + v4 + 1) * NSEQ + nbase + i];
        float x = values[(h * DVV + v4 + 2) * NSEQ + nbase + i];
        float y = values[(h * DVV + v4 + 3) * NSEQ + nbase + i];
        *(uint4*)&sm[A_V + i * STR_V + v4] =
            make_uint4(f2tf(a), f2tf(b), f2tf(x), f2tf(y));
    }
    // ones column + zero pad, STS.128
    for (int idx = t; idx < CHUNK * 2; idx += 256) {
        int i = idx >> 1, q = idx & 1;
        *(uint4*)&sm[A_V + i * STR_V + 64 + q * 4] =
            q ? make_uint4(0u, 0u, 0u, 0u)
              : make_uint4(0x3F800000u, 0u, 0u, 0u);
    }
    __syncthreads();

    // GEMM1: phi[i][m], K=64; warp tile 32x64
    {
        const int m0 = (w & 3) * 32, n0 = (w >> 2) * 64;
        float D[2][8][4] = {};
        for (int kk = 0; kk < 64; kk += 8) {
            uint32_t A[2][4], B[8][2];
            #pragma unroll
            for (int ms = 0; ms < 2; ms++) {
                int r0 = m0 + ms * 16 + g;
                A[ms][0] = sm[A_K + r0 * STR_KQ + kk + tg];
                A[ms][1] = sm[A_K + (r0 + 8) * STR_KQ + kk + tg];
                A[ms][2] = sm[A_K + r0 * STR_KQ + kk + tg + 4];
                A[ms][3] = sm[A_K + (r0 + 8) * STR_KQ + kk + tg + 4];
            }
            #pragma unroll
            for (int ns = 0; ns < 8; ns++) {
                B[ns][0] = sm[A_F + (kk + tg) * STR_F + n0 + ns * 8 + g];
                B[ns][1] = sm[A_F + (kk + tg + 4) * STR_F + n0 + ns * 8 + g];
            }
            #pragma unroll
            for (int ms = 0; ms < 2; ms++)
                #pragma unroll
                for (int ns = 0; ns < 8; ns++) mma8(D[ms][ns], A[ms], B[ns]);
        }
        // Epilogue: relu*scale -> phiT[m][i]
        #pragma unroll
        for (int ms = 0; ms < 2; ms++)
            #pragma unroll
            for (int ns = 0; ns < 8; ns++)
                #pragma unroll
                for (int e = 0; e < 4; e++) {
                    int row = m0 + ms * 16 + g + ((e >> 1) << 3);
                    int col = n0 + ns * 8 + tg * 2 + (e & 1);
                    sm[A_PT + col * STR_PT + row] =
                        f2tf(fmaxf(D[ms][ns][e], 0.f) * PHI_SCALE);
                }
    }
    __syncthreads();

    // GEMM2: [S|z][m][v+], K=128; warp tile 16x72
    {
        const int m0 = w * 16;
        float D[9][4] = {};
        for (int kk = 0; kk < CHUNK; kk += 8) {
            uint32_t A[4];
            A[0] = sm[A_PT + (m0 + g) * STR_PT + kk + tg];
            A[1] = sm[A_PT + (m0 + g + 8) * STR_PT + kk + tg];
            A[2] = sm[A_PT + (m0 + g) * STR_PT + kk + tg + 4];
            A[3] = sm[A_PT + (m0 + g + 8) * STR_PT + kk + tg + 4];
            #pragma unroll
            for (int ns = 0; ns < 9; ns++) {
                uint32_t B[2];
                B[0] = sm[A_V + (kk + tg) * STR_V + ns * 8 + g];
                B[1] = sm[A_V + (kk + tg + 4) * STR_V + ns * 8 + g];
                mma8(D[ns], A, B);
            }
        }
        float* Sg = g_S + (size_t)(h * NC + c) * MF * VP;
        #pragma unroll
        for (int ns = 0; ns < 9; ns++) {
            int colb = ns * 8 + tg * 2;
            *(float2*)&Sg[(m0 + g) * VP + colb]     = make_float2(D[ns][0], D[ns][1]);
            *(float2*)&Sg[(m0 + g + 8) * VP + colb] = make_float2(D[ns][2], D[ns][3]);
        }
    }
}

// ===========================================================================
// Kernel B: exclusive prefix over chunks of g_S (elementwise, float4)
// ===========================================================================
__global__ void __launch_bounds__(256, 1) kB()
{
    const int h = blockIdx.x;
    const int idx4 = (blockIdx.y * 256 + threadIdx.x);   // < 2304
    float4* base = (float4*)(g_S + (size_t)h * NC * MF * VP) + idx4;
    float4 v[NC];
    #pragma unroll
    for (int c = 0; c < NC; c++) v[c] = base[c * (MF * VP / 4)];
    float4 run = make_float4(0.f, 0.f, 0.f, 0.f);
    #pragma unroll
    for (int c = 0; c < NC; c++) {
        base[c * (MF * VP / 4)] = run;
        run.x += v[c].x; run.y += v[c].y; run.z += v[c].z; run.w += v[c].w;
    }
}

// ===========================================================================
// Kernel C: phi_k, phi_q, scores (masked, causal-skip), out = phiQ.S+ + Sc.V+
// (pass 2 truncated at the diagonal), norm, store
// ===========================================================================
#define C_KQ  0                      // 128x68 = 8704 -> later St 128x72 @0
#define C_F   8704                   // 64x136 = 8704 -> later (St spills into)
#define C_ST  0                      // 128x72 = 9216
#define C_V   9216                   // 128x72 = 9216
#define C_PQ  18432                  // 128x132 = 16896
#define C_PK  35328                  // 128x136 = 17408 (later Sc 128x132)
#define C_SMW 52736
#define C_SMB (C_SMW * 4)

__global__ void __launch_bounds__(256, 1)
kC(const float* __restrict__ queries, const float* __restrict__ keys,
   const float* __restrict__ values, const float* __restrict__ feat,
   float* __restrict__ out)
{
    extern __shared__ uint32_t sm[];
    const int t = threadIdx.x, w = t >> 5, lane = t & 31;
    const int g = lane >> 2, tg = lane & 3;
    const int c = blockIdx.x, h = blockIdx.y, nbase = c * CHUNK;

    // a) stage K, F
    for (int idx = t; idx < DK * CHUNK; idx += 256) {
        int i = idx & 127, d = idx >> 7;
        sm[C_KQ + i * STR_KQ + d] = f2tf(keys[(h * DK + d) * NSEQ + nbase + i]);
    }
    for (int idx = t; idx < MF * DK; idx += 256) {
        int d = idx & 63, m = idx >> 6;
        sm[C_F + d * STR_F + m] = f2tf(feat[m * DK + d]);
    }
    __syncthreads();

    const int pm0 = (w & 3) * 32, pn0 = (w >> 2) * 64;

    // b) GEMM phi_k (frags)
    float DP[2][8][4] = {};
    for (int kk = 0; kk < 64; kk += 8) {
        uint32_t A[2][4], B[8][2];
        #pragma unroll
        for (int ms = 0; ms < 2; ms++) {
            int r0 = pm0 + ms * 16 + g;
            A[ms][0] = sm[C_KQ + r0 * STR_KQ + kk + tg];
            A[ms][1] = sm[C_KQ + (r0 + 8) * STR_KQ + kk + tg];
            A[ms][2] = sm[C_KQ + r0 * STR_KQ + kk + tg + 4];
            A[ms][3] = sm[C_KQ + (r0 + 8) * STR_KQ + kk + tg + 4];
        }
        #pragma unroll
        for (int ns = 0; ns < 8; ns++) {
            B[ns][0] = sm[C_F + (kk + tg) * STR_F + pn0 + ns * 8 + g];
            B[ns][1] = sm[C_F + (kk + tg + 4) * STR_F + pn0 + ns * 8 + g];
        }
        #pragma unroll
        for (int ms = 0; ms < 2; ms++)
            #pragma unroll
            for (int ns = 0; ns < 8; ns++) mma8(DP[ms][ns], A[ms], B[ns]);
    }
    __syncthreads();   // all reads of K done

    // c) epilogue phi_k -> sPK[m][j] (transposed); restage Q into C_KQ
    #pragma unroll
    for (int ms = 0; ms < 2; ms++)
        #pragma unroll
        for (int ns = 0; ns < 8; ns++)
            #pragma unroll
            for (int e = 0; e < 4; e++) {
                int rj = pm0 + ms * 16 + g + ((e >> 1) << 3);
                int cm = pn0 + ns * 8 + tg * 2 + (e & 1);
                sm[C_PK + cm * STR_PK + rj] =
                    f2tf(fmaxf(DP[ms][ns][e], 0.f) * PHI_SCALE);
            }
    for (int idx = t; idx < DK * CHUNK; idx += 256) {
        int i = idx & 127, d = idx >> 7;
        sm[C_KQ + i * STR_KQ + d] = f2tf(queries[(h * DK + d) * NSEQ + nbase + i]);
    }
    __syncthreads();

    // d) GEMM phi_q (frags)
    #pragma unroll
    for (int ms = 0; ms < 2; ms++)
        #pragma unroll
        for (int ns = 0; ns < 8; ns++)
            #pragma unroll
            for (int e = 0; e < 4; e++) DP[ms][ns][e] = 0.f;
    for (int kk = 0; kk < 64; kk += 8) {
        uint32_t A[2][4], B[8][2];
        #pragma unroll
        for (int ms = 0; ms < 2; ms++) {
            int r0 = pm0 + ms * 16 + g;
            A[ms][0] = sm[C_KQ + r0 * STR_KQ + kk + tg];
            A[ms][1] = sm[C_KQ + (r0 + 8) * STR_KQ + kk + tg];
            A[ms][2] = sm[C_KQ + r0 * STR_KQ + kk + tg + 4];
            A[ms][3] = sm[C_KQ + (r0 + 8) * STR_KQ + kk + tg + 4];
        }
        #pragma unroll
        for (int ns = 0; ns < 8; ns++) {
            B[ns][0] = sm[C_F + (kk + tg) * STR_F + pn0 + ns * 8 + g];
            B[ns][1] = sm[C_F + (kk + tg + 4) * STR_F + pn0 + ns * 8 + g];
        }
        #pragma unroll
        for (int ms = 0; ms < 2; ms++)
            #pragma unroll
            for (int ns = 0; ns < 8; ns++) mma8(DP[ms][ns], A[ms], B[ns]);
    }
    __syncthreads();   // all reads of Q/F done -> C_KQ/C_F reusable

    // e) epilogue phi_q -> sPQ[i][m]; stage St+ (prefix [S|z]) and V+
    #pragma unroll
    for (int ms = 0; ms < 2; ms++)
        #pragma unroll
        for (int ns = 0; ns < 8; ns++)
            #pragma unroll
            for (int e = 0; e < 4; e++) {
                int ri = pm0 + ms * 16 + g + ((e >> 1) << 3);
                int cm = pn0 + ns * 8 + tg * 2 + (e & 1);
                sm[C_PQ + ri * STR_PQ + cm] =
                    f2tf(fmaxf(DP[ms][ns][e], 0.f) * PHI_SCALE);
            }
    {
        // St+: contiguous float4 loads + STS.128 (conflict-free)
        const float4* Sg4 = (const float4*)(g_S + (size_t)(h * NC + c) * MF * VP);
        for (int idx = t; idx < MF * VP / 4; idx += 256) {
            float4 x = Sg4[idx];
            *(uint4*)&sm[C_ST + idx * 4] =
                make_uint4(f2tf(x.x), f2tf(x.y), f2tf(x.z), f2tf(x.w));
        }
        // V+: 4 v-values per thread, STS.128
        for (int idx = t; idx < (DVV / 4) * CHUNK; idx += 256) {
            int j = idx & 127, v4 = (idx >> 7) << 2;
            float a = values[(h * DVV + v4 + 0) * NSEQ + nbase + j];
            float b = values[(h * DVV + v4 + 1) * NSEQ + nbase + j];
            float x = values[(h * DVV + v4 + 2) * NSEQ + nbase + j];
            float y = values[(h * DVV + v4 + 3) * NSEQ + nbase + j];
            *(uint4*)&sm[C_V + j * STR_V + v4] =
                make_uint4(f2tf(a), f2tf(b), f2tf(x), f2tf(y));
        }
        for (int idx = t; idx < CHUNK * 2; idx += 256) {
            int j = idx >> 1, q = idx & 1;
            *(uint4*)&sm[C_V + j * STR_V + 64 + q * 4] =
                q ? make_uint4(0u, 0u, 0u, 0u)
                  : make_uint4(0x3F800000u, 0u, 0u, 0u);
        }
    }
    __syncthreads();

    // f) GEMM scores: A=sPQ, B=sPK, K=128 (frags in DP).
    // Causal skip: warps whose whole 32x64 tile lies above the diagonal
    // (pn0 > pm0 + 31, i.e. warps 4 and 5) do no MMAs — DP stays 0, and the
    // mask epilogue writes the identical zeros.
    #pragma unroll
    for (int ms = 0; ms < 2; ms++)
        #pragma unroll
        for (int ns = 0; ns < 8; ns++)
            #pragma unroll
            for (int e = 0; e < 4; e++) DP[ms][ns][e] = 0.f;
    if (pn0 <= pm0 + 31) {
        for (int kk = 0; kk < CHUNK; kk += 8) {
            uint32_t A[2][4], B[8][2];
            #pragma unroll
            for (int ms = 0; ms < 2; ms++) {
                int r0 = pm0 + ms * 16 + g;
                A[ms][0] = sm[C_PQ + r0 * STR_PQ + kk + tg];
                A[ms][1] = sm[C_PQ + (r0 + 8) * STR_PQ + kk + tg];
                A[ms][2] = sm[C_PQ + r0 * STR_PQ + kk + tg + 4];
                A[ms][3] = sm[C_PQ + (r0 + 8) * STR_PQ + kk + tg + 4];
            }
            #pragma unroll
            for (int ns = 0; ns < 8; ns++) {
                B[ns][0] = sm[C_PK + (kk + tg) * STR_PK + pn0 + ns * 8 + g];
                B[ns][1] = sm[C_PK + (kk + tg + 4) * STR_PK + pn0 + ns * 8 + g];
            }
            #pragma unroll
            for (int ms = 0; ms < 2; ms++)
                #pragma unroll
                for (int ns = 0; ns < 8; ns++) mma8(DP[ms][ns], A[ms], B[ns]);
        }
    }
    __syncthreads();   // all reads of sPK done

    // g) epilogue scores: causal mask -> sSc[i][j] (overwrites C_PK region)
    #pragma unroll
    for (int ms = 0; ms < 2; ms++)
        #pragma unroll
        for (int ns = 0; ns < 8; ns++)
            #pragma unroll
            for (int e = 0; e < 4; e++) {
                int ri = pm0 + ms * 16 + g + ((e >> 1) << 3);
                int cj = pn0 + ns * 8 + tg * 2 + (e & 1);
                float s = (cj <= ri) ? DP[ms][ns][e] : 0.f;
                sm[C_PK + ri * STR_SC + cj] = f2tf(s);
            }
    __syncthreads();

    // h) GEMM out: [out|norm][i][v+] = phiQ.St+ + Sc.V+ ; warp tile 16x72
    {
        const int i0 = w * 16;
        float D[9][4] = {};
        for (int kk = 0; kk < CHUNK; kk += 8) {       // pass 1: phiQ . St+
            uint32_t A[4];
            A[0] = sm[C_PQ + (i0 + g) * STR_PQ + kk + tg];
            A[1] = sm[C_PQ + (i0 + g + 8) * STR_PQ + kk + tg];
            A[2] = sm[C_PQ + (i0 + g) * STR_PQ + kk + tg + 4];
            A[3] = sm[C_PQ + (i0 + g + 8) * STR_PQ + kk + tg + 4];
            #pragma unroll
            for (int ns = 0; ns < 9; ns++) {
                uint32_t B[2];
                B[0] = sm[C_ST + (kk + tg) * STR_ST + ns * 8 + g];
                B[1] = sm[C_ST + (kk + tg + 4) * STR_ST + ns * 8 + g];
                mma8(D[ns], A, B);
            }
        }
        // pass 2: Sc . V+, k-loop truncated at the diagonal — Sc[i][j] = 0 for
        // j > i, and rows of this warp end at i0+15, so only (i0+16)/8 k-steps
        // contribute nonzero terms.
        const int kend = i0 + 16;
        for (int kk = 0; kk < kend; kk += 8) {
            uint32_t A[4];
            A[0] = sm[C_PK + (i0 + g) * STR_SC + kk + tg];
            A[1] = sm[C_PK + (i0 + g + 8) * STR_SC + kk + tg];
            A[2] = sm[C_PK + (i0 + g) * STR_SC + kk + tg + 4];
            A[3] = sm[C_PK + (i0 + g + 8) * STR_SC + kk + tg + 4];
            #pragma unroll
            for (int ns = 0; ns < 9; ns++) {
                uint32_t B[2];
                B[0] = sm[C_V + (kk + tg) * STR_V + ns * 8 + g];
                B[1] = sm[C_V + (kk + tg + 4) * STR_V + ns * 8 + g];
                mma8(D[ns], A, B);
            }
        }
        // i) norm = column 64 (ns=8, tg=0, e=0/2) -> broadcast within row group
        float nlo = __shfl_sync(0xffffffffu, D[8][0], lane & 28);
        float nhi = __shfl_sync(0xffffffffu, D[8][2], lane & 28);
        float ilo = 1.f / nlo, ihi = 1.f / nhi;
        #pragma unroll
        for (int ns = 0; ns < 8; ns++)
            #pragma unroll
            for (int e = 0; e < 4; e++) {
                int ri = i0 + g + ((e >> 1) << 3);
                int v  = ns * 8 + tg * 2 + (e & 1);
                out[(h * DVV + v) * NSEQ + nbase + ri] =
                    D[ns][e] * ((e >> 1) ? ihi : ilo);
            }
    }
}

// ===========================================================================
extern "C" void kernel_launch(void* const* d_in, const int* in_sizes, int n_in,
                              void* d_out, int out_size)
{
    const float* keys    = (const float*)d_in[0];
    const float* values  = (const float*)d_in[1];
    const float* queries = (const float*)d_in[2];
    const float* feat    = (const float*)d_in[3];
    float* out = (float*)d_out;

    cudaFuncSetAttribute(kA, cudaFuncAttributeMaxDynamicSharedMemorySize, A_SMB);
    cudaFuncSetAttribute(kC, cudaFuncAttributeMaxDynamicSharedMemorySize, C_SMB);

    kA<<<dim3(NC, BH), 256, A_SMB>>>(keys, values, feat);
    kB<<<dim3(BH, 9), 256>>>();
    kC<<<dim3(NC, BH), 256, C_SMB>>>(queries, keys, values, feat, out);
}

// round 16
// speedup vs baseline: 1.3221x; 1.1846x over previous
#include <cuda_runtime.h>
#include <cstdint>

#define BH    8
#define DK    64
#define DVV   64
#define NSEQ  2048
#define MF    128
#define CHUNK 128
#define NC    16
#define VP    72          // DV padded: col 64 = ones (z / norm), 65..71 = 0

#define PHI_SCALE 0.08838834764831845f   // 1/sqrt(128)

// Per-(head,chunk) fused state [S | z | pad] : [m][VP], fp32.
// kB converts to exclusive prefix over chunks.
__device__ float g_S[BH * NC * MF * VP];   // 4.7 MB

// ---------------------------------------------------------------------------
__device__ __forceinline__ uint32_t f2tf(float f) {
    uint32_t r; asm("cvt.rna.tf32.f32 %0, %1;" : "=r"(r) : "f"(f)); return r;
}
__device__ __forceinline__ void mma8(float* d, const uint32_t* A, const uint32_t* B) {
    asm volatile("mma.sync.aligned.m16n8k8.row.col.f32.tf32.tf32.f32 "
                 "{%0,%1,%2,%3}, {%4,%5,%6,%7}, {%8,%9}, {%0,%1,%2,%3};"
                 : "+f"(d[0]), "+f"(d[1]), "+f"(d[2]), "+f"(d[3])
                 : "r"(A[0]), "r"(A[1]), "r"(A[2]), "r"(A[3]), "r"(B[0]), "r"(B[1]));
}
// cp.async staging (raw fp32 bits -> consumed as tf32 by HW truncation)
__device__ __forceinline__ void cpa4(uint32_t saddr, const void* g) {
    asm volatile("cp.async.ca.shared.global [%0], [%1], 4;" :: "r"(saddr), "l"(g));
}
__device__ __forceinline__ void cpa16(uint32_t saddr, const void* g) {
    asm volatile("cp.async.cg.shared.global [%0], [%1], 16;" :: "r"(saddr), "l"(g));
}
#define CP_COMMIT() asm volatile("cp.async.commit_group;" ::: "memory")
#define CP_WAIT0()  asm volatile("cp.async.wait_group 0;" ::: "memory")

// Smem strides (words), chosen so fragment LDS are bank-conflict-free:
// A-operand row stride ≡ 4 (mod 32); B-operand row stride ≡ 8 (mod 32).
#define STR_KQ 68    // [i][d]  A
#define STR_F  136   // [d][m]  B
#define STR_PT 132   // [m][i]  A (kA phi^T)
#define STR_V  72    // [i][v]  B
#define STR_PQ 132   // [i][m]  A
#define STR_PK 136   // [m][j]  B
#define STR_SC 132   // [i][j]  A
#define STR_ST 72    // [m][v]  B

// ===========================================================================
// Kernel A: per (h,c): phi = relu(Kc F^T)*s ;  [S|z] = phi^T [V;1]
// ===========================================================================
#define A_K   0                       // 128 x 68  = 8704
#define A_F   8704                    // 64 x 136  = 8704
#define A_PT  17408                   // 128 x 132 = 16896
#define A_V   34304                   // 128 x 72  = 9216
#define A_SMW 43520
#define A_SMB (A_SMW * 4)

__global__ void __launch_bounds__(256, 1)
kA(const float* __restrict__ keys, const float* __restrict__ values,
   const float* __restrict__ feat)
{
    extern __shared__ uint32_t sm[];
    const uint32_t sb = (uint32_t)__cvta_generic_to_shared(sm);
    const int t = threadIdx.x, w = t >> 5, lane = t & 31;
    const int g = lane >> 2, tg = lane & 3;
    const int c = blockIdx.x, h = blockIdx.y, nbase = c * CHUNK;

    // Stage via cp.async (raw bits; tf32-rz at MMA consumption)
    for (int idx = t; idx < DK * CHUNK; idx += 256) {
        int i = idx & 127, d = idx >> 7;
        cpa4(sb + 4u * (A_K + i * STR_KQ + d), keys + (h * DK + d) * NSEQ + nbase + i);
    }
    for (int idx = t; idx < MF * DK; idx += 256) {
        int d = idx & 63, m = idx >> 6;
        cpa4(sb + 4u * (A_F + d * STR_F + m), feat + m * DK + d);
    }
    for (int idx = t; idx < DVV * CHUNK; idx += 256) {
        int i = idx & 127, v = idx >> 7;
        cpa4(sb + 4u * (A_V + i * STR_V + v), values + (h * DVV + v) * NSEQ + nbase + i);
    }
    CP_COMMIT();
    // ones column + zero pad, plain STS.128 (disjoint addresses)
    for (int idx = t; idx < CHUNK * 2; idx += 256) {
        int i = idx >> 1, q = idx & 1;
        *(uint4*)&sm[A_V + i * STR_V + 64 + q * 4] =
            q ? make_uint4(0u, 0u, 0u, 0u)
              : make_uint4(0x3F800000u, 0u, 0u, 0u);
    }
    CP_WAIT0();
    __syncthreads();

    // GEMM1: phi[i][m], K=64; warp tile 32x64
    {
        const int m0 = (w & 3) * 32, n0 = (w >> 2) * 64;
        float D[2][8][4] = {};
        for (int kk = 0; kk < 64; kk += 8) {
            uint32_t A[2][4], B[8][2];
            #pragma unroll
            for (int ms = 0; ms < 2; ms++) {
                int r0 = m0 + ms * 16 + g;
                A[ms][0] = sm[A_K + r0 * STR_KQ + kk + tg];
                A[ms][1] = sm[A_K + (r0 + 8) * STR_KQ + kk + tg];
                A[ms][2] = sm[A_K + r0 * STR_KQ + kk + tg + 4];
                A[ms][3] = sm[A_K + (r0 + 8) * STR_KQ + kk + tg + 4];
            }
            #pragma unroll
            for (int ns = 0; ns < 8; ns++) {
                B[ns][0] = sm[A_F + (kk + tg) * STR_F + n0 + ns * 8 + g];
                B[ns][1] = sm[A_F + (kk + tg + 4) * STR_F + n0 + ns * 8 + g];
            }
            #pragma unroll
            for (int ms = 0; ms < 2; ms++)
                #pragma unroll
                for (int ns = 0; ns < 8; ns++) mma8(D[ms][ns], A[ms], B[ns]);
        }
        // Epilogue: relu*scale -> phiT[m][i]
        #pragma unroll
        for (int ms = 0; ms < 2; ms++)
            #pragma unroll
            for (int ns = 0; ns < 8; ns++)
                #pragma unroll
                for (int e = 0; e < 4; e++) {
                    int row = m0 + ms * 16 + g + ((e >> 1) << 3);
                    int col = n0 + ns * 8 + tg * 2 + (e & 1);
                    sm[A_PT + col * STR_PT + row] =
                        f2tf(fmaxf(D[ms][ns][e], 0.f) * PHI_SCALE);
                }
    }
    __syncthreads();

    // GEMM2: [S|z][m][v+], K=128; warp tile 16x72
    {
        const int m0 = w * 16;
        float D[9][4] = {};
        for (int kk = 0; kk < CHUNK; kk += 8) {
            uint32_t A[4];
            A[0] = sm[A_PT + (m0 + g) * STR_PT + kk + tg];
            A[1] = sm[A_PT + (m0 + g + 8) * STR_PT + kk + tg];
            A[2] = sm[A_PT + (m0 + g) * STR_PT + kk + tg + 4];
            A[3] = sm[A_PT + (m0 + g + 8) * STR_PT + kk + tg + 4];
            #pragma unroll
            for (int ns = 0; ns < 9; ns++) {
                uint32_t B[2];
                B[0] = sm[A_V + (kk + tg) * STR_V + ns * 8 + g];
                B[1] = sm[A_V + (kk + tg + 4) * STR_V + ns * 8 + g];
                mma8(D[ns], A, B);
            }
        }
        float* Sg = g_S + (size_t)(h * NC + c) * MF * VP;
        #pragma unroll
        for (int ns = 0; ns < 9; ns++) {
            int colb = ns * 8 + tg * 2;
            *(float2*)&Sg[(m0 + g) * VP + colb]     = make_float2(D[ns][0], D[ns][1]);
            *(float2*)&Sg[(m0 + g + 8) * VP + colb] = make_float2(D[ns][2], D[ns][3]);
        }
    }
}

// ===========================================================================
// Kernel B: exclusive prefix over chunks of g_S (elementwise, float4)
// ===========================================================================
__global__ void __launch_bounds__(256, 1) kB()
{
    const int h = blockIdx.x;
    const int idx4 = (blockIdx.y * 256 + threadIdx.x);   // < 2304
    float4* base = (float4*)(g_S + (size_t)h * NC * MF * VP) + idx4;
    float4 v[NC];
    #pragma unroll
    for (int c = 0; c < NC; c++) v[c] = base[c * (MF * VP / 4)];
    float4 run = make_float4(0.f, 0.f, 0.f, 0.f);
    #pragma unroll
    for (int c = 0; c < NC; c++) {
        base[c * (MF * VP / 4)] = run;
        run.x += v[c].x; run.y += v[c].y; run.z += v[c].z; run.w += v[c].w;
    }
}

// ===========================================================================
// Kernel C: phi_k, phi_q, scores (masked, causal-skip), out = phiQ.S+ + Sc.V+
// (pass 2 truncated at the diagonal), norm, store
// ===========================================================================
#define C_KQ  0                      // 128x68 = 8704 -> later St 128x72 @0
#define C_F   8704                   // 64x136 = 8704 -> later (St spills into)
#define C_ST  0                      // 128x72 = 9216
#define C_V   9216                   // 128x72 = 9216
#define C_PQ  18432                  // 128x132 = 16896
#define C_PK  35328                  // 128x136 = 17408 (later Sc 128x132)
#define C_SMW 52736
#define C_SMB (C_SMW * 4)

__global__ void __launch_bounds__(256, 1)
kC(const float* __restrict__ queries, const float* __restrict__ keys,
   const float* __restrict__ values, const float* __restrict__ feat,
   float* __restrict__ out)
{
    extern __shared__ uint32_t sm[];
    const uint32_t sb = (uint32_t)__cvta_generic_to_shared(sm);
    const int t = threadIdx.x, w = t >> 5, lane = t & 31;
    const int g = lane >> 2, tg = lane & 3;
    const int c = blockIdx.x, h = blockIdx.y, nbase = c * CHUNK;

    // a) stage K, F via cp.async
    for (int idx = t; idx < DK * CHUNK; idx += 256) {
        int i = idx & 127, d = idx >> 7;
        cpa4(sb + 4u * (C_KQ + i * STR_KQ + d), keys + (h * DK + d) * NSEQ + nbase + i);
    }
    for (int idx = t; idx < MF * DK; idx += 256) {
        int d = idx & 63, m = idx >> 6;
        cpa4(sb + 4u * (C_F + d * STR_F + m), feat + m * DK + d);
    }
    CP_COMMIT();
    CP_WAIT0();
    __syncthreads();

    const int pm0 = (w & 3) * 32, pn0 = (w >> 2) * 64;

    // b) GEMM phi_k (frags)
    float DP[2][8][4] = {};
    for (int kk = 0; kk < 64; kk += 8) {
        uint32_t A[2][4], B[8][2];
        #pragma unroll
        for (int ms = 0; ms < 2; ms++) {
            int r0 = pm0 + ms * 16 + g;
            A[ms][0] = sm[C_KQ + r0 * STR_KQ + kk + tg];
            A[ms][1] = sm[C_KQ + (r0 + 8) * STR_KQ + kk + tg];
            A[ms][2] = sm[C_KQ + r0 * STR_KQ + kk + tg + 4];
            A[ms][3] = sm[C_KQ + (r0 + 8) * STR_KQ + kk + tg + 4];
        }
        #pragma unroll
        for (int ns = 0; ns < 8; ns++) {
            B[ns][0] = sm[C_F + (kk + tg) * STR_F + pn0 + ns * 8 + g];
            B[ns][1] = sm[C_F + (kk + tg + 4) * STR_F + pn0 + ns * 8 + g];
        }
        #pragma unroll
        for (int ms = 0; ms < 2; ms++)
            #pragma unroll
            for (int ns = 0; ns < 8; ns++) mma8(DP[ms][ns], A[ms], B[ns]);
    }
    __syncthreads();   // all reads of K done

    // c) issue Q restage (async, overlaps epilogue); epilogue phi_k -> sPK[m][j]
    for (int idx = t; idx < DK * CHUNK; idx += 256) {
        int i = idx & 127, d = idx >> 7;
        cpa4(sb + 4u * (C_KQ + i * STR_KQ + d), queries + (h * DK + d) * NSEQ + nbase + i);
    }
    CP_COMMIT();
    #pragma unroll
    for (int ms = 0; ms < 2; ms++)
        #pragma unroll
        for (int ns = 0; ns < 8; ns++)
            #pragma unroll
            for (int e = 0; e < 4; e++) {
                int rj = pm0 + ms * 16 + g + ((e >> 1) << 3);
                int cm = pn0 + ns * 8 + tg * 2 + (e & 1);
                sm[C_PK + cm * STR_PK + rj] =
                    f2tf(fmaxf(DP[ms][ns][e], 0.f) * PHI_SCALE);
            }
    CP_WAIT0();
    __syncthreads();

    // d) GEMM phi_q (frags)
    #pragma unroll
    for (int ms = 0; ms < 2; ms++)
        #pragma unroll
        for (int ns = 0; ns < 8; ns++)
            #pragma unroll
            for (int e = 0; e < 4; e++) DP[ms][ns][e] = 0.f;
    for (int kk = 0; kk < 64; kk += 8) {
        uint32_t A[2][4], B[8][2];
        #pragma unroll
        for (int ms = 0; ms < 2; ms++) {
            int r0 = pm0 + ms * 16 + g;
            A[ms][0] = sm[C_KQ + r0 * STR_KQ + kk + tg];
            A[ms][1] = sm[C_KQ + (r0 + 8) * STR_KQ + kk + tg];
            A[ms][2] = sm[C_KQ + r0 * STR_KQ + kk + tg + 4];
            A[ms][3] = sm[C_KQ + (r0 + 8) * STR_KQ + kk + tg + 4];
        }
        #pragma unroll
        for (int ns = 0; ns < 8; ns++) {
            B[ns][0] = sm[C_F + (kk + tg) * STR_F + pn0 + ns * 8 + g];
            B[ns][1] = sm[C_F + (kk + tg + 4) * STR_F + pn0 + ns * 8 + g];
        }
        #pragma unroll
        for (int ms = 0; ms < 2; ms++)
            #pragma unroll
            for (int ns = 0; ns < 8; ns++) mma8(DP[ms][ns], A[ms], B[ns]);
    }
    __syncthreads();   // all reads of Q/F done -> C_KQ/C_F reusable

    // e) issue St+/V+ staging (async, overlaps epilogue); epilogue phi_q -> sPQ
    {
        const float* Sg = g_S + (size_t)(h * NC + c) * MF * VP;   // [m][v] contiguous
        for (int idx = t; idx < MF * VP / 4; idx += 256)
            cpa16(sb + 4u * (C_ST + idx * 4), (const float4*)Sg + idx);
        for (int idx = t; idx < DVV * CHUNK; idx += 256) {
            int j = idx & 127, v = idx >> 7;
            cpa4(sb + 4u * (C_V + j * STR_V + v), values + (h * DVV + v) * NSEQ + nbase + j);
        }
        CP_COMMIT();
    }
    #pragma unroll
    for (int ms = 0; ms < 2; ms++)
        #pragma unroll
        for (int ns = 0; ns < 8; ns++)
            #pragma unroll
            for (int e = 0; e < 4; e++) {
                int ri = pm0 + ms * 16 + g + ((e >> 1) << 3);
                int cm = pn0 + ns * 8 + tg * 2 + (e & 1);
                sm[C_PQ + ri * STR_PQ + cm] =
                    f2tf(fmaxf(DP[ms][ns][e], 0.f) * PHI_SCALE);
            }
    for (int idx = t; idx < CHUNK * 2; idx += 256) {
        int j = idx >> 1, q = idx & 1;
        *(uint4*)&sm[C_V + j * STR_V + 64 + q * 4] =
            q ? make_uint4(0u, 0u, 0u, 0u)
              : make_uint4(0x3F800000u, 0u, 0u, 0u);
    }
    CP_WAIT0();
    __syncthreads();

    // f) GEMM scores: A=sPQ, B=sPK, K=128 (frags in DP).
    // Causal skip: warps whose whole 32x64 tile lies above the diagonal
    // (pn0 > pm0 + 31, i.e. warps 4 and 5) do no MMAs — DP stays 0, and the
    // mask epilogue writes the identical zeros.
    #pragma unroll
    for (int ms = 0; ms < 2; ms++)
        #pragma unroll
        for (int ns = 0; ns < 8; ns++)
            #pragma unroll
            for (int e = 0; e < 4; e++) DP[ms][ns][e] = 0.f;
    if (pn0 <= pm0 + 31) {
        for (int kk = 0; kk < CHUNK; kk += 8) {
            uint32_t A[2][4], B[8][2];
            #pragma unroll
            for (int ms = 0; ms < 2; ms++) {
                int r0 = pm0 + ms * 16 + g;
                A[ms][0] = sm[C_PQ + r0 * STR_PQ + kk + tg];
                A[ms][1] = sm[C_PQ + (r0 + 8) * STR_PQ + kk + tg];
                A[ms][2] = sm[C_PQ + r0 * STR_PQ + kk + tg + 4];
                A[ms][3] = sm[C_PQ + (r0 + 8) * STR_PQ + kk + tg + 4];
            }
            #pragma unroll
            for (int ns = 0; ns < 8; ns++) {
                B[ns][0] = sm[C_PK + (kk + tg) * STR_PK + pn0 + ns * 8 + g];
                B[ns][1] = sm[C_PK + (kk + tg + 4) * STR_PK + pn0 + ns * 8 + g];
            }
            #pragma unroll
            for (int ms = 0; ms < 2; ms++)
                #pragma unroll
                for (int ns = 0; ns < 8; ns++) mma8(DP[ms][ns], A[ms], B[ns]);
        }
    }
    __syncthreads();   // all reads of sPK done

    // g) epilogue scores: causal mask -> sSc[i][j] (overwrites C_PK region)
    #pragma unroll
    for (int ms = 0; ms < 2; ms++)
        #pragma unroll
        for (int ns = 0; ns < 8; ns++)
            #pragma unroll
            for (int e = 0; e < 4; e++) {
                int ri = pm0 + ms * 16 + g + ((e >> 1) << 3);
                int cj = pn0 + ns * 8 + tg * 2 + (e & 1);
                float s = (cj <= ri) ? DP[ms][ns][e] : 0.f;
                sm[C_PK + ri * STR_SC + cj] = f2tf(s);
            }
    __syncthreads();

    // h) GEMM out: [out|norm][i][v+] = phiQ.St+ + Sc.V+ ; warp tile 16x72
    {
        const int i0 = w * 16;
        float D[9][4] = {};
        for (int kk = 0; kk < CHUNK; kk += 8) {       // pass 1: phiQ . St+
            uint32_t A[4];
            A[0] = sm[C_PQ + (i0 + g) * STR_PQ + kk + tg];
            A[1] = sm[C_PQ + (i0 + g + 8) * STR_PQ + kk + tg];
            A[2] = sm[C_PQ + (i0 + g) * STR_PQ + kk + tg + 4];
            A[3] = sm[C_PQ + (i0 + g + 8) * STR_PQ + kk + tg + 4];
            #pragma unroll
            for (int ns = 0; ns < 9; ns++) {
                uint32_t B[2];
                B[0] = sm[C_ST + (kk + tg) * STR_ST + ns * 8 + g];
                B[1] = sm[C_ST + (kk + tg + 4) * STR_ST + ns * 8 + g];
                mma8(D[ns], A, B);
            }
        }
        // pass 2: Sc . V+, k-loop truncated at the diagonal — Sc[i][j] = 0 for
        // j > i, and rows of this warp end at i0+15, so only (i0+16)/8 k-steps
        // contribute nonzero terms.
        const int kend = i0 + 16;
        for (int kk = 0; kk < kend; kk += 8) {
            uint32_t A[4];
            A[0] = sm[C_PK + (i0 + g) * STR_SC + kk + tg];
            A[1] = sm[C_PK + (i0 + g + 8) * STR_SC + kk + tg];
            A[2] = sm[C_PK + (i0 + g) * STR_SC + kk + tg + 4];
            A[3] = sm[C_PK + (i0 + g + 8) * STR_SC + kk + tg + 4];
            #pragma unroll
            for (int ns = 0; ns < 9; ns++) {
                uint32_t B[2];
                B[0] = sm[C_V + (kk + tg) * STR_V + ns * 8 + g];
                B[1] = sm[C_V + (kk + tg + 4) * STR_V + ns * 8 + g];
                mma8(D[ns], A, B);
            }
        }
        // i) norm = column 64 (ns=8, tg=0, e=0/2) -> broadcast within row group
        float nlo = __shfl_sync(0xffffffffu, D[8][0], lane & 28);
        float nhi = __shfl_sync(0xffffffffu, D[8][2], lane & 28);
        float ilo = 1.f / nlo, ihi = 1.f / nhi;
        #pragma unroll
        for (int ns = 0; ns < 8; ns++)
            #pragma unroll
            for (int e = 0; e < 4; e++) {
                int ri = i0 + g + ((e >> 1) << 3);
                int v  = ns * 8 + tg * 2 + (e & 1);
                out[(h * DVV + v) * NSEQ + nbase + ri] =
                    D[ns][e] * ((e >> 1) ? ihi : ilo);
            }
    }
}

// ===========================================================================
extern "C" void kernel_launch(void* const* d_in, const int* in_sizes, int n_in,
                              void* d_out, int out_size)
{
    const float* keys    = (const float*)d_in[0];
    const float* values  = (const float*)d_in[1];
    const float* queries = (const float*)d_in[2];
    const float* feat    = (const float*)d_in[3];
    float* out = (float*)d_out;

    cudaFuncSetAttribute(kA, cudaFuncAttributeMaxDynamicSharedMemorySize, A_SMB);
    cudaFuncSetAttribute(kC, cudaFuncAttributeMaxDynamicSharedMemorySize, C_SMB);

    kA<<<dim3(NC, BH), 256, A_SMB>>>(keys, values, feat);
    kB<<<dim3(BH, 9), 256>>>();
    kC<<<dim3(NC, BH), 256, C_SMB>>>(queries, keys, values, feat, out);
}

// round 17
// speedup vs baseline: 1.3247x; 1.0019x over previous
#include <cuda_runtime.h>
#include <cstdint>

#define BH    8
#define DK    64
#define DVV   64
#define NSEQ  2048
#define MF    128
#define CHUNK 128
#define NC    16
#define VP    72          // DV padded: col 64 = ones (z / norm), 65..71 = 0

#define PHI_SCALE 0.08838834764831845f   // 1/sqrt(128)

// Per-(head,chunk) fused state [S | z | pad] : [m][VP], fp32.
// kB converts to exclusive prefix over chunks.
__device__ float g_S[BH * NC * MF * VP];   // 4.7 MB

// ---------------------------------------------------------------------------
__device__ __forceinline__ uint32_t f2tf(float f) {
    uint32_t r; asm("cvt.rna.tf32.f32 %0, %1;" : "=r"(r) : "f"(f)); return r;
}
__device__ __forceinline__ void mma8(float* d, const uint32_t* A, const uint32_t* B) {
    asm volatile("mma.sync.aligned.m16n8k8.row.col.f32.tf32.tf32.f32 "
                 "{%0,%1,%2,%3}, {%4,%5,%6,%7}, {%8,%9}, {%0,%1,%2,%3};"
                 : "+f"(d[0]), "+f"(d[1]), "+f"(d[2]), "+f"(d[3])
                 : "r"(A[0]), "r"(A[1]), "r"(A[2]), "r"(A[3]), "r"(B[0]), "r"(B[1]));
}
// cp.async staging (raw fp32 bits -> consumed as tf32 by HW truncation)
__device__ __forceinline__ void cpa4(uint32_t saddr, const void* g) {
    asm volatile("cp.async.ca.shared.global [%0], [%1], 4;" :: "r"(saddr), "l"(g));
}
__device__ __forceinline__ void cpa16(uint32_t saddr, const void* g) {
    asm volatile("cp.async.cg.shared.global [%0], [%1], 16;" :: "r"(saddr), "l"(g));
}
#define CP_COMMIT() asm volatile("cp.async.commit_group;" ::: "memory")
#define CP_WAIT0()  asm volatile("cp.async.wait_group 0;" ::: "memory")

// Smem strides (words), chosen so fragment LDS are bank-conflict-free:
// A-operand row stride ≡ 4 (mod 32); B-operand row stride ≡ 8 (mod 32).
#define STR_KQ 68    // [i][d]  A
#define STR_F  136   // [d][m]  B
#define STR_PT 132   // [m][i]  A (kA phi^T)
#define STR_V  72    // [i][v]  B
#define STR_PQ 132   // [i][m]  A
#define STR_PK 136   // [m][j]  B
#define STR_SC 132   // [i][j]  A
#define STR_ST 72    // [m][v]  B

// ===========================================================================
// Kernel A: per (h,c): phi = relu(Kc F^T)*s ;  [S|z] = phi^T [V;1]
// ===========================================================================
#define A_K   0                       // 128 x 68  = 8704
#define A_F   8704                    // 64 x 136  = 8704
#define A_PT  17408                   // 128 x 132 = 16896
#define A_V   34304                   // 128 x 72  = 9216
#define A_SMW 43520
#define A_SMB (A_SMW * 4)

__global__ void __launch_bounds__(256, 1)
kA(const float* __restrict__ keys, const float* __restrict__ values,
   const float* __restrict__ feat)
{
    extern __shared__ uint32_t sm[];
    const uint32_t sb = (uint32_t)__cvta_generic_to_shared(sm);
    const int t = threadIdx.x, w = t >> 5, lane = t & 31;
    const int g = lane >> 2, tg = lane & 3;
    const int c = blockIdx.x, h = blockIdx.y, nbase = c * CHUNK;

    // Stage via cp.async (raw bits; tf32-rz at MMA consumption)
    for (int idx = t; idx < DK * CHUNK; idx += 256) {
        int i = idx & 127, d = idx >> 7;
        cpa4(sb + 4u * (A_K + i * STR_KQ + d), keys + (h * DK + d) * NSEQ + nbase + i);
    }
    for (int idx = t; idx < MF * DK; idx += 256) {
        int d = idx & 63, m = idx >> 6;
        cpa4(sb + 4u * (A_F + d * STR_F + m), feat + m * DK + d);
    }
    for (int idx = t; idx < DVV * CHUNK; idx += 256) {
        int i = idx & 127, v = idx >> 7;
        cpa4(sb + 4u * (A_V + i * STR_V + v), values + (h * DVV + v) * NSEQ + nbase + i);
    }
    CP_COMMIT();
    // ones column + zero pad, plain STS.128 (disjoint addresses)
    for (int idx = t; idx < CHUNK * 2; idx += 256) {
        int i = idx >> 1, q = idx & 1;
        *(uint4*)&sm[A_V + i * STR_V + 64 + q * 4] =
            q ? make_uint4(0u, 0u, 0u, 0u)
              : make_uint4(0x3F800000u, 0u, 0u, 0u);
    }
    CP_WAIT0();
    __syncthreads();

    // GEMM1: phi[i][m], K=64; warp tile 32x64
    {
        const int m0 = (w & 3) * 32, n0 = (w >> 2) * 64;
        float D[2][8][4] = {};
        for (int kk = 0; kk < 64; kk += 8) {
            uint32_t A[2][4], B[8][2];
            #pragma unroll
            for (int ms = 0; ms < 2; ms++) {
                int r0 = m0 + ms * 16 + g;
                A[ms][0] = sm[A_K + r0 * STR_KQ + kk + tg];
                A[ms][1] = sm[A_K + (r0 + 8) * STR_KQ + kk + tg];
                A[ms][2] = sm[A_K + r0 * STR_KQ + kk + tg + 4];
                A[ms][3] = sm[A_K + (r0 + 8) * STR_KQ + kk + tg + 4];
            }
            #pragma unroll
            for (int ns = 0; ns < 8; ns++) {
                B[ns][0] = sm[A_F + (kk + tg) * STR_F + n0 + ns * 8 + g];
                B[ns][1] = sm[A_F + (kk + tg + 4) * STR_F + n0 + ns * 8 + g];
            }
            #pragma unroll
            for (int ms = 0; ms < 2; ms++)
                #pragma unroll
                for (int ns = 0; ns < 8; ns++) mma8(D[ms][ns], A[ms], B[ns]);
        }
        // Epilogue: relu*scale -> phiT[m][i]
        #pragma unroll
        for (int ms = 0; ms < 2; ms++)
            #pragma unroll
            for (int ns = 0; ns < 8; ns++)
                #pragma unroll
                for (int e = 0; e < 4; e++) {
                    int row = m0 + ms * 16 + g + ((e >> 1) << 3);
                    int col = n0 + ns * 8 + tg * 2 + (e & 1);
                    sm[A_PT + col * STR_PT + row] =
                        f2tf(fmaxf(D[ms][ns][e], 0.f) * PHI_SCALE);
                }
    }
    __syncthreads();

    // GEMM2: [S|z][m][v+], K=128; warp tile 16x72
    {
        const int m0 = w * 16;
        float D[9][4] = {};
        for (int kk = 0; kk < CHUNK; kk += 8) {
            uint32_t A[4];
            A[0] = sm[A_PT + (m0 + g) * STR_PT + kk + tg];
            A[1] = sm[A_PT + (m0 + g + 8) * STR_PT + kk + tg];
            A[2] = sm[A_PT + (m0 + g) * STR_PT + kk + tg + 4];
            A[3] = sm[A_PT + (m0 + g + 8) * STR_PT + kk + tg + 4];
            #pragma unroll
            for (int ns = 0; ns < 9; ns++) {
                uint32_t B[2];
                B[0] = sm[A_V + (kk + tg) * STR_V + ns * 8 + g];
                B[1] = sm[A_V + (kk + tg + 4) * STR_V + ns * 8 + g];
                mma8(D[ns], A, B);
            }
        }
        float* Sg = g_S + (size_t)(h * NC + c) * MF * VP;
        #pragma unroll
        for (int ns = 0; ns < 9; ns++) {
            int colb = ns * 8 + tg * 2;
            *(float2*)&Sg[(m0 + g) * VP + colb]     = make_float2(D[ns][0], D[ns][1]);
            *(float2*)&Sg[(m0 + g + 8) * VP + colb] = make_float2(D[ns][2], D[ns][3]);
        }
    }
}

// ===========================================================================
// Kernel B: exclusive prefix over chunks of g_S (elementwise, float4)
// ===========================================================================
__global__ void __launch_bounds__(256, 1) kB()
{
    const int h = blockIdx.x;
    const int idx4 = (blockIdx.y * 256 + threadIdx.x);   // < 2304
    float4* base = (float4*)(g_S + (size_t)h * NC * MF * VP) + idx4;
    float4 v[NC];
    #pragma unroll
    for (int c = 0; c < NC; c++) v[c] = base[c * (MF * VP / 4)];
    float4 run = make_float4(0.f, 0.f, 0.f, 0.f);
    #pragma unroll
    for (int c = 0; c < NC; c++) {
        base[c * (MF * VP / 4)] = run;
        run.x += v[c].x; run.y += v[c].y; run.z += v[c].z; run.w += v[c].w;
    }
}

// ===========================================================================
// Kernel C: phi_k, phi_q, scores (masked; SMSP-balanced tile map + fully-
// masked-block skip), out = phiQ.S+ + Sc.V+ (pass 2 truncated at the diagonal;
// SMSP-balanced i-tile map), norm, store
// ===========================================================================
#define C_KQ  0                      // 128x68 = 8704 -> later St 128x72 @0
#define C_F   8704                   // 64x136 = 8704
#define C_ST  0                      // 128x72 = 9216
#define C_V   9216                   // 128x72 = 9216
#define C_PQ  18432                  // 128x132 = 16896
#define C_PK  35328                  // 128x136 = 17408 (later Sc 128x132)
#define C_SMW 52736
#define C_SMB (C_SMW * 4)

__global__ void __launch_bounds__(256, 1)
kC(const float* __restrict__ queries, const float* __restrict__ keys,
   const float* __restrict__ values, const float* __restrict__ feat,
   float* __restrict__ out)
{
    extern __shared__ uint32_t sm[];
    const uint32_t sb = (uint32_t)__cvta_generic_to_shared(sm);
    const int t = threadIdx.x, w = t >> 5, lane = t & 31;
    const int g = lane >> 2, tg = lane & 3;
    const int c = blockIdx.x, h = blockIdx.y, nbase = c * CHUNK;

    // a) stage K, F via cp.async
    for (int idx = t; idx < DK * CHUNK; idx += 256) {
        int i = idx & 127, d = idx >> 7;
        cpa4(sb + 4u * (C_KQ + i * STR_KQ + d), keys + (h * DK + d) * NSEQ + nbase + i);
    }
    for (int idx = t; idx < MF * DK; idx += 256) {
        int d = idx & 63, m = idx >> 6;
        cpa4(sb + 4u * (C_F + d * STR_F + m), feat + m * DK + d);
    }
    CP_COMMIT();
    CP_WAIT0();
    __syncthreads();

    const int pm0 = (w & 3) * 32, pn0 = (w >> 2) * 64;

    // b) GEMM phi_k (frags)
    float DP[2][8][4] = {};
    for (int kk = 0; kk < 64; kk += 8) {
        uint32_t A[2][4], B[8][2];
        #pragma unroll
        for (int ms = 0; ms < 2; ms++) {
            int r0 = pm0 + ms * 16 + g;
            A[ms][0] = sm[C_KQ + r0 * STR_KQ + kk + tg];
            A[ms][1] = sm[C_KQ + (r0 + 8) * STR_KQ + kk + tg];
            A[ms][2] = sm[C_KQ + r0 * STR_KQ + kk + tg + 4];
            A[ms][3] = sm[C_KQ + (r0 + 8) * STR_KQ + kk + tg + 4];
        }
        #pragma unroll
        for (int ns = 0; ns < 8; ns++) {
            B[ns][0] = sm[C_F + (kk + tg) * STR_F + pn0 + ns * 8 + g];
            B[ns][1] = sm[C_F + (kk + tg + 4) * STR_F + pn0 + ns * 8 + g];
        }
        #pragma unroll
        for (int ms = 0; ms < 2; ms++)
            #pragma unroll
            for (int ns = 0; ns < 8; ns++) mma8(DP[ms][ns], A[ms], B[ns]);
    }
    __syncthreads();   // all reads of K done

    // c) issue Q restage (async, overlaps epilogue); epilogue phi_k -> sPK[m][j]
    for (int idx = t; idx < DK * CHUNK; idx += 256) {
        int i = idx & 127, d = idx >> 7;
        cpa4(sb + 4u * (C_KQ + i * STR_KQ + d), queries + (h * DK + d) * NSEQ + nbase + i);
    }
    CP_COMMIT();
    #pragma unroll
    for (int ms = 0; ms < 2; ms++)
        #pragma unroll
        for (int ns = 0; ns < 8; ns++)
            #pragma unroll
            for (int e = 0; e < 4; e++) {
                int rj = pm0 + ms * 16 + g + ((e >> 1) << 3);
                int cm = pn0 + ns * 8 + tg * 2 + (e & 1);
                sm[C_PK + cm * STR_PK + rj] =
                    f2tf(fmaxf(DP[ms][ns][e], 0.f) * PHI_SCALE);
            }
    CP_WAIT0();
    __syncthreads();

    // d) GEMM phi_q (frags)
    #pragma unroll
    for (int ms = 0; ms < 2; ms++)
        #pragma unroll
        for (int ns = 0; ns < 8; ns++)
            #pragma unroll
            for (int e = 0; e < 4; e++) DP[ms][ns][e] = 0.f;
    for (int kk = 0; kk < 64; kk += 8) {
        uint32_t A[2][4], B[8][2];
        #pragma unroll
        for (int ms = 0; ms < 2; ms++) {
            int r0 = pm0 + ms * 16 + g;
            A[ms][0] = sm[C_KQ + r0 * STR_KQ + kk + tg];
            A[ms][1] = sm[C_KQ + (r0 + 8) * STR_KQ + kk + tg];
            A[ms][2] = sm[C_KQ + r0 * STR_KQ + kk + tg + 4];
            A[ms][3] = sm[C_KQ + (r0 + 8) * STR_KQ + kk + tg + 4];
        }
        #pragma unroll
        for (int ns = 0; ns < 8; ns++) {
            B[ns][0] = sm[C_F + (kk + tg) * STR_F + pn0 + ns * 8 + g];
            B[ns][1] = sm[C_F + (kk + tg + 4) * STR_F + pn0 + ns * 8 + g];
        }
        #pragma unroll
        for (int ms = 0; ms < 2; ms++)
            #pragma unroll
            for (int ns = 0; ns < 8; ns++) mma8(DP[ms][ns], A[ms], B[ns]);
    }
    __syncthreads();   // all reads of Q/F done -> C_KQ/C_F reusable

    // e) issue St+/V+ staging (async, overlaps epilogue); epilogue phi_q -> sPQ
    {
        const float* Sg = g_S + (size_t)(h * NC + c) * MF * VP;   // [m][v] contiguous
        for (int idx = t; idx < MF * VP / 4; idx += 256)
            cpa16(sb + 4u * (C_ST + idx * 4), (const float4*)Sg + idx);
        for (int idx = t; idx < DVV * CHUNK; idx += 256) {
            int j = idx & 127, v = idx >> 7;
            cpa4(sb + 4u * (C_V + j * STR_V + v), values + (h * DVV + v) * NSEQ + nbase + j);
        }
        CP_COMMIT();
    }
    #pragma unroll
    for (int ms = 0; ms < 2; ms++)
        #pragma unroll
        for (int ns = 0; ns < 8; ns++)
            #pragma unroll
            for (int e = 0; e < 4; e++) {
                int ri = pm0 + ms * 16 + g + ((e >> 1) << 3);
                int cm = pn0 + ns * 8 + tg * 2 + (e & 1);
                sm[C_PQ + ri * STR_PQ + cm] =
                    f2tf(fmaxf(DP[ms][ns][e], 0.f) * PHI_SCALE);
            }
    for (int idx = t; idx < CHUNK * 2; idx += 256) {
        int j = idx >> 1, q = idx & 1;
        *(uint4*)&sm[C_V + j * STR_V + 64 + q * 4] =
            q ? make_uint4(0u, 0u, 0u, 0u)
              : make_uint4(0x3F800000u, 0u, 0u, 0u);
    }
    CP_WAIT0();
    __syncthreads();

    // f) GEMM scores: A=sPQ, B=sPK, K=128 (frags in DP).
    // SMSP-balanced warp->tile map (heavy tiles paired with light/empty ones):
    //   w0:(32,0) w1:(64,0) w2:(96,0) w3:(96,64) w4:(0,0) w5:(64,64)
    //   w6:(0,64) w7:(32,64)  (w6, w7 fully masked -> no MMAs)
    // Per-tile ns-blocks with all columns > row_max are fully masked -> skipped
    // (their DP stays 0; the mask epilogue writes identical zeros).
    int spm0, spn0;
    if      (w <  3) { spm0 = (w + 1) * 32; spn0 = 0;  }
    else if (w == 3) { spm0 = 96;           spn0 = 64; }
    else if (w == 4) { spm0 = 0;            spn0 = 0;  }
    else if (w == 5) { spm0 = 64;           spn0 = 64; }
    else             { spm0 = (w - 6) * 32; spn0 = 64; }
    int nsEnd = 0;
    if (spn0 <= spm0 + 31) {
        nsEnd = ((spm0 + 31 - spn0) >> 3) + 1;
        if (nsEnd > 8) nsEnd = 8;
    }
    #pragma unroll
    for (int ms = 0; ms < 2; ms++)
        #pragma unroll
        for (int ns = 0; ns < 8; ns++)
            #pragma unroll
            for (int e = 0; e < 4; e++) DP[ms][ns][e] = 0.f;
    if (nsEnd > 0) {
        for (int kk = 0; kk < CHUNK; kk += 8) {
            uint32_t A[2][4];
            #pragma unroll
            for (int ms = 0; ms < 2; ms++) {
                int r0 = spm0 + ms * 16 + g;
                A[ms][0] = sm[C_PQ + r0 * STR_PQ + kk + tg];
                A[ms][1] = sm[C_PQ + (r0 + 8) * STR_PQ + kk + tg];
                A[ms][2] = sm[C_PQ + r0 * STR_PQ + kk + tg + 4];
                A[ms][3] = sm[C_PQ + (r0 + 8) * STR_PQ + kk + tg + 4];
            }
            #pragma unroll
            for (int ns = 0; ns < 8; ns++) {
                if (ns >= nsEnd) break;
                uint32_t B[2];
                B[0] = sm[C_PK + (kk + tg) * STR_PK + spn0 + ns * 8 + g];
                B[1] = sm[C_PK + (kk + tg + 4) * STR_PK + spn0 + ns * 8 + g];
                mma8(DP[0][ns], A[0], B);
                mma8(DP[1][ns], A[1], B);
            }
        }
    }
    __syncthreads();   // all reads of sPK done

    // g) epilogue scores: causal mask -> sSc[i][j] (overwrites C_PK region)
    #pragma unroll
    for (int ms = 0; ms < 2; ms++)
        #pragma unroll
        for (int ns = 0; ns < 8; ns++)
            #pragma unroll
            for (int e = 0; e < 4; e++) {
                int ri = spm0 + ms * 16 + g + ((e >> 1) << 3);
                int cj = spn0 + ns * 8 + tg * 2 + (e & 1);
                float s = (cj <= ri) ? DP[ms][ns][e] : 0.f;
                sm[C_PK + ri * STR_SC + cj] = f2tf(s);
            }
    __syncthreads();

    // h) GEMM out: [out|norm][i][v+] = phiQ.St+ + Sc.V+ ; warp tile 16x72.
    // SMSP-balanced i-tile map: it = w<4 ? 7-w : w-4, so every SMSP carries
    // pass-2 ksteps 2*(8-s) + 2*(s+1) = 18 (was 12..24).
    {
        const int it = (w < 4) ? (7 - w) : (w - 4);
        const int i0 = it * 16;
        float D[9][4] = {};
        for (int kk = 0; kk < CHUNK; kk += 8) {       // pass 1: phiQ . St+
            uint32_t A[4];
            A[0] = sm[C_PQ + (i0 + g) * STR_PQ + kk + tg];
            A[1] = sm[C_PQ + (i0 + g + 8) * STR_PQ + kk + tg];
            A[2] = sm[C_PQ + (i0 + g) * STR_PQ + kk + tg + 4];
            A[3] = sm[C_PQ + (i0 + g + 8) * STR_PQ + kk + tg + 4];
            #pragma unroll
            for (int ns = 0; ns < 9; ns++) {
                uint32_t B[2];
                B[0] = sm[C_ST + (kk + tg) * STR_ST + ns * 8 + g];
                B[1] = sm[C_ST + (kk + tg + 4) * STR_ST + ns * 8 + g];
                mma8(D[ns], A, B);
            }
        }
        // pass 2: Sc . V+, k-loop truncated at the diagonal — Sc[i][j] = 0 for
        // j > i, and rows of this warp end at i0+15, so only (i0+16)/8 k-steps
        // contribute nonzero terms.
        const int kend = i0 + 16;
        for (int kk = 0; kk < kend; kk += 8) {
            uint32_t A[4];
            A[0] = sm[C_PK + (i0 + g) * STR_SC + kk + tg];
            A[1] = sm[C_PK + (i0 + g + 8) * STR_SC + kk + tg];
            A[2] = sm[C_PK + (i0 + g) * STR_SC + kk + tg + 4];
            A[3] = sm[C_PK + (i0 + g + 8) * STR_SC + kk + tg + 4];
            #pragma unroll
            for (int ns = 0; ns < 9; ns++) {
                uint32_t B[2];
                B[0] = sm[C_V + (kk + tg) * STR_V + ns * 8 + g];
                B[1] = sm[C_V + (kk + tg + 4) * STR_V + ns * 8 + g];
                mma8(D[ns], A, B);
            }
        }
        // i) norm = column 64 (ns=8, tg=0, e=0/2) -> broadcast within row group
        float nlo = __shfl_sync(0xffffffffu, D[8][0], lane & 28);
        float nhi = __shfl_sync(0xffffffffu, D[8][2], lane & 28);
        float ilo = 1.f / nlo, ihi = 1.f / nhi;
        #pragma unroll
        for (int ns = 0; ns < 8; ns++)
            #pragma unroll
            for (int e = 0; e < 4; e++) {
                int ri = i0 + g + ((e >> 1) << 3);
                int v  = ns * 8 + tg * 2 + (e & 1);
                out[(h * DVV + v) * NSEQ + nbase + ri] =
                    D[ns][e] * ((e >> 1) ? ihi : ilo);
            }
    }
}

// ===========================================================================
extern "C" void kernel_launch(void* const* d_in, const int* in_sizes, int n_in,
                              void* d_out, int out_size)
{
    const float* keys    = (const float*)d_in[0];
    const float* values  = (const float*)d_in[1];
    const float* queries = (const float*)d_in[2];
    const float* feat    = (const float*)d_in[3];
    float* out = (float*)d_out;

    cudaFuncSetAttribute(kA, cudaFuncAttributeMaxDynamicSharedMemorySize, A_SMB);
    cudaFuncSetAttribute(kC, cudaFuncAttributeMaxDynamicSharedMemorySize, C_SMB);

    kA<<<dim3(NC, BH), 256, A_SMB>>>(keys, values, feat);
    kB<<<dim3(BH, 9), 256>>>();
    kC<<<dim3(NC, BH), 256, C_SMB>>>(queries, keys, values, feat, out);
}